// round 6
// baseline (speedup 1.0000x reference)
#include <cuda_runtime.h>
#include <cuda_fp16.h>

#define NN 5000      // nodes per level
#define BB 1024      // batch
#define KK 16        // fan-in
#define NLEV 9       // level applications
#define CH 8         // batch chunk per block (fp16 x 8 = 16 B per node = one LDS.128)
#define NBLK (BB / CH)   // 128 persistent blocks
#define NTHR 512
#define NEG_SLOPE 0.1f

// int16 copy of the predecessor indices (values < 5000 < 65536): halves idx LDG traffic
__device__ unsigned short g_idx16[NLEV * NN * KK];   // 1.44 MB

__global__ void prep_idx(const int* __restrict__ sidx) {
    int i = blockIdx.x * 256 + threadIdx.x;
    if (i < NLEV * NN * KK) g_idx16[i] = (unsigned short)sidx[i];
}

// One gather-accumulate: one LDS.128 (8 fp16) + 8 FMA
#define GATH(s, wk) do {                                           \
    uint4 v = src[(s)];                                            \
    float2 f0 = __half22float2(*(const __half2*)&v.x);             \
    float2 f1 = __half22float2(*(const __half2*)&v.y);             \
    float2 f2 = __half22float2(*(const __half2*)&v.z);             \
    float2 f3 = __half22float2(*(const __half2*)&v.w);             \
    a0 = fmaf(f0.x, (wk), a0);  a1 = fmaf(f0.y, (wk), a1);         \
    a2 = fmaf(f1.x, (wk), a2);  a3 = fmaf(f1.y, (wk), a3);         \
    a4 = fmaf(f2.x, (wk), a4);  a5 = fmaf(f2.y, (wk), a5);         \
    a6 = fmaf(f3.x, (wk), a6);  a7 = fmaf(f3.y, (wk), a7);         \
} while (0)

__global__ __launch_bounds__(NTHR, 1) void topo_kernel(
    const float* __restrict__ x,      // [B, N]
    const float* __restrict__ w,      // [NLEV, N, K]
    const float* __restrict__ bias,   // [NLEV, N]
    float* __restrict__ out)          // [B, N]
{
    // ping-pong activation slices: [2][NN] x 16 B (8 fp16 batch lanes per node)
    extern __shared__ __align__(16) uint4 sbuf[];

    const int t = threadIdx.x;
    const int c = blockIdx.x;          // batch chunk id

    // ---- prologue: x[c*CH + j][n] -> buf0[n].h[j] (fp16) ----
    {
        half* h0 = reinterpret_cast<half*>(sbuf);
#pragma unroll
        for (int j = 0; j < CH; j++) {
            const float* xr = x + (size_t)(c * CH + j) * NN;
            for (int n = t; n < NN; n += NTHR)
                h0[n * CH + j] = __float2half_rn(xr[n]);
        }
    }
    __syncthreads();

    // ---- 9 levels entirely in SMEM ----
    int sel = 0;
    for (int l = 0; l < NLEV; l++) {
        const uint4* __restrict__ src = sel ? (sbuf + NN) : sbuf;
        uint4* __restrict__ dst       = sel ? sbuf : (sbuf + NN);
        const uint4*  __restrict__ ib = reinterpret_cast<const uint4*>(g_idx16 + (size_t)l * NN * KK);
        const float4* __restrict__ wb = reinterpret_cast<const float4*>(w + (size_t)l * NN * KK);
        const float*  __restrict__ bb = bias + (size_t)l * NN;

        for (int n = t; n < NN; n += NTHR) {
            uint4 iA = ib[n * 2 + 0];          // idx k0..k7 (8 x u16)
            uint4 iB = ib[n * 2 + 1];          // idx k8..k15
            float4 w0 = wb[n * 4 + 0];
            float4 w1 = wb[n * 4 + 1];
            float4 w2 = wb[n * 4 + 2];
            float4 w3 = wb[n * 4 + 3];
            float bv = bb[n];
            float a0 = bv, a1 = bv, a2 = bv, a3 = bv;
            float a4 = bv, a5 = bv, a6 = bv, a7 = bv;

            GATH(iA.x & 0xFFFFu, w0.x);  GATH(iA.x >> 16, w0.y);
            GATH(iA.y & 0xFFFFu, w0.z);  GATH(iA.y >> 16, w0.w);
            GATH(iA.z & 0xFFFFu, w1.x);  GATH(iA.z >> 16, w1.y);
            GATH(iA.w & 0xFFFFu, w1.z);  GATH(iA.w >> 16, w1.w);
            GATH(iB.x & 0xFFFFu, w2.x);  GATH(iB.x >> 16, w2.y);
            GATH(iB.y & 0xFFFFu, w2.z);  GATH(iB.y >> 16, w2.w);
            GATH(iB.z & 0xFFFFu, w3.x);  GATH(iB.z >> 16, w3.y);
            GATH(iB.w & 0xFFFFu, w3.z);  GATH(iB.w >> 16, w3.w);

            a0 = a0 > 0.0f ? a0 : NEG_SLOPE * a0;
            a1 = a1 > 0.0f ? a1 : NEG_SLOPE * a1;
            a2 = a2 > 0.0f ? a2 : NEG_SLOPE * a2;
            a3 = a3 > 0.0f ? a3 : NEG_SLOPE * a3;
            a4 = a4 > 0.0f ? a4 : NEG_SLOPE * a4;
            a5 = a5 > 0.0f ? a5 : NEG_SLOPE * a5;
            a6 = a6 > 0.0f ? a6 : NEG_SLOPE * a6;
            a7 = a7 > 0.0f ? a7 : NEG_SLOPE * a7;

            __half2 h0 = __floats2half2_rn(a0, a1);
            __half2 h1 = __floats2half2_rn(a2, a3);
            __half2 h2 = __floats2half2_rn(a4, a5);
            __half2 h3 = __floats2half2_rn(a6, a7);
            uint4 o;
            o.x = *reinterpret_cast<unsigned int*>(&h0);
            o.y = *reinterpret_cast<unsigned int*>(&h1);
            o.z = *reinterpret_cast<unsigned int*>(&h2);
            o.w = *reinterpret_cast<unsigned int*>(&h3);
            dst[n] = o;                       // STS.128, conflict-free
        }
        __syncthreads();
        sel ^= 1;
    }

    // ---- epilogue: buf[sel][n].h[j] -> out[c*CH + j][n] ----
    {
        const half* hf = reinterpret_cast<const half*>(sel ? (sbuf + NN) : sbuf);
#pragma unroll
        for (int j = 0; j < CH; j++) {
            float* orow = out + (size_t)(c * CH + j) * NN;
            for (int n = t; n < NN; n += NTHR)
                orow[n] = __half2float(hf[n * CH + j]);
        }
    }
}

// ---------------------------------------------------------------------------
extern "C" void kernel_launch(void* const* d_in, const int* in_sizes, int n_in,
                              void* d_out, int out_size) {
    const float* x    = (const float*)d_in[0];   // [B, N] fp32
    const int*   sidx = (const int*)d_in[1];     // [NLEV, N, K] int32
    const float* w    = (const float*)d_in[2];   // [NLEV, N, K] fp32
    const float* bias = (const float*)d_in[3];   // [NLEV, N]    fp32
    float* out = (float*)d_out;                  // [B, N] fp32

    const int smem_bytes = 2 * NN * 16;          // 160,000 B ping-pong
    cudaFuncSetAttribute(topo_kernel, cudaFuncAttributeMaxDynamicSharedMemorySize, smem_bytes);

    int tot = NLEV * NN * KK;
    prep_idx<<<(tot + 255) / 256, 256>>>(sidx);

    topo_kernel<<<NBLK, NTHR, smem_bytes>>>(x, w, bias, out);
}